// round 1
// baseline (speedup 1.0000x reference)
#include <cuda_runtime.h>
#include <math.h>

#define NB 4
#define NS 256
#define ND 768
#define NF 3072
#define NL 4
#define NH 12
#define NDH 64
#define NR (NB*NS)   /* 1024 rows */
#define NT 6

// ---------------- scratch (static device globals; no allocs) ----------------
static __device__ float g_xin[NR*ND];
static __device__ float g_prev[NR*ND];
static __device__ float g_q[NR*ND];
static __device__ float g_k[NR*ND];
static __device__ float g_v[NR*ND];
static __device__ float g_ctx[NR*ND];
static __device__ float g_aout[NR*ND];
static __device__ float g_x1[NR*ND];
static __device__ float g_fout[NR*ND];
static __device__ float g_ffh[NR*NF];
static __device__ float g_mem[NL*NR*ND];
static __device__ float g_cnt[NL*NR*ND];

// ---------------- helpers ----------------
__device__ __forceinline__ float gelu_f(float x) {
    // jax.nn.gelu approximate=True (tanh form)
    float x3 = x * x * x;
    float t = tanhf(0.7978845608028654f * (x + 0.044715f * x3));
    return 0.5f * x * (1.0f + t);
}

__device__ __forceinline__ float blk_sum(float v, volatile float* red, int tid) {
    #pragma unroll
    for (int o = 16; o; o >>= 1) v += __shfl_xor_sync(0xffffffffu, v, o);
    if ((tid & 31) == 0) red[tid >> 5] = v;
    __syncthreads();
    float tot = 0.f;
    #pragma unroll
    for (int i = 0; i < 8; i++) tot += red[i];
    return tot;
}

// ---------------- x_in = u + seg_emb[segment_ids]; also writes z[0] ----------------
__global__ __launch_bounds__(256) void xin_kernel(
    const float* __restrict__ u, const int* __restrict__ seg,
    const float* __restrict__ semb, float* __restrict__ z0)
{
    int idx = blockIdx.x * 256 + threadIdx.x;          // 0 .. NR*ND-1
    int srow = idx / ND;
    int d = idx - srow * ND;
    float val = u[idx] + semb[seg[srow] * ND + d];
    g_xin[idx] = val;
    z0[idx] = val;
}

// ---------------- fp32 tiled GEMM: C[M=1024,N] = A[M,K] @ W[K,N] + bias, opt GELU ----------------
__global__ __launch_bounds__(256) void gemm_kernel(
    const float* __restrict__ A, const float* __restrict__ W,
    const float* __restrict__ bias, float* __restrict__ C,
    int N, int K, int do_gelu)
{
    __shared__ float As[16][65];   // k-major, padded (conflict-free transpose stores)
    __shared__ float Ws[16][64];

    int bx = blockIdx.x, by = blockIdx.y;
    int tid = threadIdx.x;
    int tx = tid & 15, ty = tid >> 4;
    int arow = tid >> 2, acol = (tid & 3) << 2;
    int wrow = tid >> 4, wcol = (tid & 15) << 2;

    const float* Ap = A + (size_t)(by * 64 + arow) * K + acol;
    const float* Wp = W + (size_t)wrow * N + bx * 64 + wcol;

    float acc[4][4] = {};

    for (int k0 = 0; k0 < K; k0 += 16) {
        float4 av = *(const float4*)(Ap + k0);
        float4 wv = *(const float4*)(Wp + (size_t)k0 * N);
        __syncthreads();
        As[acol + 0][arow] = av.x;
        As[acol + 1][arow] = av.y;
        As[acol + 2][arow] = av.z;
        As[acol + 3][arow] = av.w;
        *(float4*)&Ws[wrow][wcol] = wv;
        __syncthreads();
        #pragma unroll
        for (int kk = 0; kk < 16; kk++) {
            float a0 = As[kk][ty * 4 + 0];
            float a1 = As[kk][ty * 4 + 1];
            float a2 = As[kk][ty * 4 + 2];
            float a3 = As[kk][ty * 4 + 3];
            float4 bv = *(const float4*)&Ws[kk][tx * 4];
            acc[0][0] = fmaf(a0, bv.x, acc[0][0]); acc[0][1] = fmaf(a0, bv.y, acc[0][1]);
            acc[0][2] = fmaf(a0, bv.z, acc[0][2]); acc[0][3] = fmaf(a0, bv.w, acc[0][3]);
            acc[1][0] = fmaf(a1, bv.x, acc[1][0]); acc[1][1] = fmaf(a1, bv.y, acc[1][1]);
            acc[1][2] = fmaf(a1, bv.z, acc[1][2]); acc[1][3] = fmaf(a1, bv.w, acc[1][3]);
            acc[2][0] = fmaf(a2, bv.x, acc[2][0]); acc[2][1] = fmaf(a2, bv.y, acc[2][1]);
            acc[2][2] = fmaf(a2, bv.z, acc[2][2]); acc[2][3] = fmaf(a2, bv.w, acc[2][3]);
            acc[3][0] = fmaf(a3, bv.x, acc[3][0]); acc[3][1] = fmaf(a3, bv.y, acc[3][1]);
            acc[3][2] = fmaf(a3, bv.z, acc[3][2]); acc[3][3] = fmaf(a3, bv.w, acc[3][3]);
        }
    }

    int n0 = bx * 64 + tx * 4;
    #pragma unroll
    for (int i = 0; i < 4; i++) {
        int m = by * 64 + ty * 4 + i;
        float4 o;
        o.x = acc[i][0] + bias[n0 + 0];
        o.y = acc[i][1] + bias[n0 + 1];
        o.z = acc[i][2] + bias[n0 + 2];
        o.w = acc[i][3] + bias[n0 + 3];
        if (do_gelu) {
            o.x = gelu_f(o.x); o.y = gelu_f(o.y); o.z = gelu_f(o.z); o.w = gelu_f(o.w);
        }
        *(float4*)&C[(size_t)m * N + n0] = o;
    }
}

// ---------------- fused attention: scores -> softmax -> asum += p/6 -> ctx ----------------
// grid: (rowblock 0..3, h 0..11, b 0..3), 256 threads.
#define ATTN_SMEM_FLOATS (64*257 + 256*64 + 64*256 + 64*64)

__global__ __launch_bounds__(256) void attn_kernel(
    const float* __restrict__ q, const float* __restrict__ k, const float* __restrict__ v,
    const float* __restrict__ mask, float* __restrict__ asum, float* __restrict__ ctx,
    float inv6)
{
    extern __shared__ float sm[];
    float* Ks = sm;                     // [64][257]  d-major (padded)
    float* Vs = sm + 64 * 257;          // [256][64]  j-major
    float* Ss = Vs + 256 * 64;          // [64][256]  probs
    float* Qs = Ss + 64 * 256;          // [64][64]

    const int rb = blockIdx.x, h = blockIdx.y, b = blockIdx.z;
    const int tid = threadIdx.x;
    const int lane = tid & 31, w = tid >> 5;
    const int i0 = rb * 64;

    const int dq = (tid & 15) * 4;      // 16 threads cover one 64-float row
    const int jb = tid >> 4;            // 0..15

    const float* kb = k + (size_t)b * NS * ND + h * NDH;
    const float* vb = v + (size_t)b * NS * ND + h * NDH;
    const float* qb = q + ((size_t)b * NS + i0) * ND + h * NDH;

    #pragma unroll
    for (int it = 0; it < 16; it++) {
        int j = jb + it * 16;
        float4 kv = *(const float4*)(kb + (size_t)j * ND + dq);
        Ks[(dq + 0) * 257 + j] = kv.x;
        Ks[(dq + 1) * 257 + j] = kv.y;
        Ks[(dq + 2) * 257 + j] = kv.z;
        Ks[(dq + 3) * 257 + j] = kv.w;
        float4 vv = *(const float4*)(vb + (size_t)j * ND + dq);
        *(float4*)&Vs[j * 64 + dq] = vv;
    }
    #pragma unroll
    for (int it = 0; it < 4; it++) {
        int i = jb + it * 16;
        float4 qv = *(const float4*)(qb + (size_t)i * ND + dq);
        *(float4*)&Qs[i * 64 + dq] = qv;
    }
    __syncthreads();

    float extr[8];
    #pragma unroll
    for (int jj = 0; jj < 8; jj++)
        extr[jj] = (1.0f - mask[b * NS + lane + 32 * jj]) * -10000.0f;

    // ---- scores: warp w owns local rows r0..r0+7, lane owns keys lane+32*jj ----
    float acc[8][8];
    #pragma unroll
    for (int r = 0; r < 8; r++)
        #pragma unroll
        for (int jj = 0; jj < 8; jj++) acc[r][jj] = 0.f;

    const int r0 = w * 8;
    for (int d = 0; d < 64; d++) {
        float kr[8];
        #pragma unroll
        for (int jj = 0; jj < 8; jj++) kr[jj] = Ks[d * 257 + lane + 32 * jj];
        #pragma unroll
        for (int r = 0; r < 8; r++) {
            float qv = Qs[(r0 + r) * 64 + d];
            #pragma unroll
            for (int jj = 0; jj < 8; jj++) acc[r][jj] = fmaf(qv, kr[jj], acc[r][jj]);
        }
    }

    // ---- softmax per row (registers + shuffles), asum accumulate, probs -> smem ----
    #pragma unroll
    for (int r = 0; r < 8; r++) {
        float mx = -3.0e38f;
        #pragma unroll
        for (int jj = 0; jj < 8; jj++) {
            float s = acc[r][jj] * 0.125f + extr[jj];   // /sqrt(64) + ext mask
            acc[r][jj] = s;
            mx = fmaxf(mx, s);
        }
        #pragma unroll
        for (int o = 16; o; o >>= 1) mx = fmaxf(mx, __shfl_xor_sync(0xffffffffu, mx, o));
        float sum = 0.f;
        #pragma unroll
        for (int jj = 0; jj < 8; jj++) { float e = expf(acc[r][jj] - mx); acc[r][jj] = e; sum += e; }
        #pragma unroll
        for (int o = 16; o; o >>= 1) sum += __shfl_xor_sync(0xffffffffu, sum, o);
        float rinv = 1.0f / sum;
        int i = r0 + r;
        float* ar = asum + (((size_t)(b * NH + h)) * NS + (i0 + i)) * NS;
        #pragma unroll
        for (int jj = 0; jj < 8; jj++) {
            float p = acc[r][jj] * rinv;
            int j = lane + 32 * jj;
            Ss[i * 256 + j] = p;
            ar[j] += p * inv6;
        }
    }
    __syncwarp();   // warp reads its own rows' probs across lanes

    // ---- ctx = probs @ V : lane owns d = lane, lane+32 ----
    float c0[8], c1[8];
    #pragma unroll
    for (int r = 0; r < 8; r++) { c0[r] = 0.f; c1[r] = 0.f; }
    for (int j = 0; j < 256; j++) {
        float v0 = Vs[j * 64 + lane];
        float v1 = Vs[j * 64 + lane + 32];
        #pragma unroll
        for (int r = 0; r < 8; r++) {
            float p = Ss[(r0 + r) * 256 + j];
            c0[r] = fmaf(p, v0, c0[r]);
            c1[r] = fmaf(p, v1, c1[r]);
        }
    }
    #pragma unroll
    for (int r = 0; r < 8; r++) {
        size_t base = ((size_t)b * NS + i0 + r0 + r) * ND + h * NDH;
        ctx[base + lane] = c0[r];
        ctx[base + lane + 32] = c1[r];
    }
}

// ---------------- fused residual + LayerNorm ----------------
__global__ __launch_bounds__(256) void add_ln_kernel(
    const float* __restrict__ x, const float* __restrict__ y,
    const float* __restrict__ g, const float* __restrict__ bb,
    float* __restrict__ out)
{
    __shared__ float redA[8], redB[8];
    int row = blockIdx.x, tid = threadIdx.x;
    const float* xr = x + (size_t)row * ND;
    const float* yr = y + (size_t)row * ND;
    float s0 = xr[tid] + yr[tid];
    float s1 = xr[tid + 256] + yr[tid + 256];
    float s2 = xr[tid + 512] + yr[tid + 512];
    float mean = blk_sum(s0 + s1 + s2, redA, tid) * (1.0f / 768.0f);
    float d0 = s0 - mean, d1 = s1 - mean, d2 = s2 - mean;
    float var = blk_sum(d0 * d0 + d1 * d1 + d2 * d2, redB, tid) * (1.0f / 768.0f);
    float rstd = 1.0f / sqrtf(var + 1e-12f);
    float* orow = out + (size_t)row * ND;
    orow[tid]       = g[tid]       * d0 * rstd + bb[tid];
    orow[tid + 256] = g[tid + 256] * d1 * rstd + bb[tid + 256];
    orow[tid + 512] = g[tid + 512] * d2 * rstd + bb[tid + 512];
}

// ---------------- fused residual + LN + IF spike update ----------------
__global__ __launch_bounds__(256) void add_ln_spike_kernel(
    const float* __restrict__ x, const float* __restrict__ y,
    const float* __restrict__ g, const float* __restrict__ bb,
    float* __restrict__ mem, float* __restrict__ cnt, float* __restrict__ prev,
    float invt, float* __restrict__ zout)
{
    __shared__ float redA[8], redB[8];
    int row = blockIdx.x, tid = threadIdx.x;
    const float* xr = x + (size_t)row * ND;
    const float* yr = y + (size_t)row * ND;
    float s0 = xr[tid] + yr[tid];
    float s1 = xr[tid + 256] + yr[tid + 256];
    float s2 = xr[tid + 512] + yr[tid + 512];
    float mean = blk_sum(s0 + s1 + s2, redA, tid) * (1.0f / 768.0f);
    float d0 = s0 - mean, d1 = s1 - mean, d2 = s2 - mean;
    float var = blk_sum(d0 * d0 + d1 * d1 + d2 * d2, redB, tid) * (1.0f / 768.0f);
    float rstd = 1.0f / sqrtf(var + 1e-12f);

    float dd[3] = {d0, d1, d2};
    #pragma unroll
    for (int e = 0; e < 3; e++) {
        int col = tid + 256 * e;
        size_t idx = (size_t)row * ND + col;
        float cur = g[col] * dd[e] * rstd + bb[col];
        float m = mem[idx] + cur;
        float spk = (m >= 1.0f) ? 1.0f : 0.0f;   // VTH = 1
        mem[idx] = m - spk;
        float cn = cnt[idx] + spk;
        cnt[idx] = cn;
        float pv = cn * invt;
        prev[idx] = pv;
        if (zout) zout[idx] = pv;                // at t=T-1: cnt/T = rate
    }
}

// ---------------- launch ----------------
extern "C" void kernel_launch(void* const* d_in, const int* in_sizes, int n_in,
                              void* d_out, int out_size)
{
    const float* u    = (const float*)d_in[0];
    const int*   seg  = (const int*)d_in[1];
    const float* mask = (const float*)d_in[2];
    const float* semb = (const float*)d_in[3];
    const float* Wq   = (const float*)d_in[4];  const float* bq = (const float*)d_in[5];
    const float* Wk   = (const float*)d_in[6];  const float* bk = (const float*)d_in[7];
    const float* Wv   = (const float*)d_in[8];  const float* bv = (const float*)d_in[9];
    const float* Wo   = (const float*)d_in[10]; const float* bo = (const float*)d_in[11];
    const float* ln1g = (const float*)d_in[12]; const float* ln1b = (const float*)d_in[13];
    const float* W1   = (const float*)d_in[14]; const float* b1 = (const float*)d_in[15];
    const float* W2   = (const float*)d_in[16]; const float* b2 = (const float*)d_in[17];
    const float* ln2g = (const float*)d_in[18]; const float* ln2b = (const float*)d_in[19];
    // d_in[20] = time_step (always 6; hardcoded as NT)

    float* out  = (float*)d_out;
    float* z    = out;                              // [5,B,S,D]
    float* attn = out + (size_t)5 * NR * ND;        // [L,B,H,S,S]

    void* p;
    float *xin, *prev, *q, *k, *v, *ctx, *aout, *x1, *fout, *ffh, *mem, *cnt;
    cudaGetSymbolAddress(&p, g_xin);  xin  = (float*)p;
    cudaGetSymbolAddress(&p, g_prev); prev = (float*)p;
    cudaGetSymbolAddress(&p, g_q);    q    = (float*)p;
    cudaGetSymbolAddress(&p, g_k);    k    = (float*)p;
    cudaGetSymbolAddress(&p, g_v);    v    = (float*)p;
    cudaGetSymbolAddress(&p, g_ctx);  ctx  = (float*)p;
    cudaGetSymbolAddress(&p, g_aout); aout = (float*)p;
    cudaGetSymbolAddress(&p, g_x1);   x1   = (float*)p;
    cudaGetSymbolAddress(&p, g_fout); fout = (float*)p;
    cudaGetSymbolAddress(&p, g_ffh);  ffh  = (float*)p;
    cudaGetSymbolAddress(&p, g_mem);  mem  = (float*)p;
    cudaGetSymbolAddress(&p, g_cnt);  cnt  = (float*)p;

    cudaFuncSetAttribute(attn_kernel, cudaFuncAttributeMaxDynamicSharedMemorySize,
                         ATTN_SMEM_FLOATS * 4);

    cudaMemsetAsync(mem, 0, sizeof(float) * (size_t)NL * NR * ND);
    cudaMemsetAsync(cnt, 0, sizeof(float) * (size_t)NL * NR * ND);
    cudaMemsetAsync(attn, 0, sizeof(float) * (size_t)NL * NB * NH * NS * NS);

    xin_kernel<<<(NR * ND) / 256, 256>>>(u, seg, semb, z);

    dim3 gD(12, 16), gF(48, 16);
    const float inv6 = 1.0f / 6.0f;

    for (int t = 0; t < NT; t++) {
        float invt = 1.0f / (float)(t + 1);
        const float* xcur = xin;
        for (int l = 0; l < NL; l++) {
            gemm_kernel<<<gD, 256>>>(xcur, Wq + (size_t)l * ND * ND, bq + l * ND, q, ND, ND, 0);
            gemm_kernel<<<gD, 256>>>(xcur, Wk + (size_t)l * ND * ND, bk + l * ND, k, ND, ND, 0);
            gemm_kernel<<<gD, 256>>>(xcur, Wv + (size_t)l * ND * ND, bv + l * ND, v, ND, ND, 0);
            attn_kernel<<<dim3(4, 12, 4), 256, ATTN_SMEM_FLOATS * 4>>>(
                q, k, v, mask, attn + (size_t)l * NB * NH * NS * NS, ctx, inv6);
            gemm_kernel<<<gD, 256>>>(ctx, Wo + (size_t)l * ND * ND, bo + l * ND, aout, ND, ND, 0);
            add_ln_kernel<<<NR, 256>>>(xcur, aout, ln1g + l * ND, ln1b + l * ND, x1);
            gemm_kernel<<<gF, 256>>>(x1, W1 + (size_t)l * ND * NF, b1 + l * NF, ffh, NF, ND, 1);
            gemm_kernel<<<gD, 256>>>(ffh, W2 + (size_t)l * NF * ND, b2 + l * ND, fout, ND, NF, 0);
            add_ln_spike_kernel<<<NR, 256>>>(x1, fout, ln2g + l * ND, ln2b + l * ND,
                mem + (size_t)l * NR * ND, cnt + (size_t)l * NR * ND, prev, invt,
                (t == NT - 1) ? (z + (size_t)(1 + l) * NR * ND) : (float*)0);
            xcur = prev;
        }
    }
}

// round 2
// speedup vs baseline: 1.9330x; 1.9330x over previous
#include <cuda_runtime.h>
#include <math.h>

#define NB 4
#define NS 256
#define ND 768
#define NF 3072
#define NL 4
#define NH 12
#define NDH 64
#define NR (NB*NS)   /* 1024 rows */
#define NT 6
#define N3 (3*ND)    /* 2304 */

// ---------------- scratch (static device globals; no allocs) ----------------
static __device__ float g_xin [NR*ND];
static __device__ float g_prev[NR*ND];
static __device__ float g_qkv [NR*N3];
static __device__ float g_ctx [NR*ND];
static __device__ float g_aout[2*NR*ND];   // O-proj split-K partials
static __device__ float g_x1  [NR*ND];
static __device__ float g_fout[4*NR*ND];   // FFN2 split-K partials
static __device__ float g_ffh [NR*NF];
static __device__ float g_cur0[NR*ND];     // layer-0 block output (constant over t)
static __device__ float g_mem [NL*NR*ND];
static __device__ float g_cnt [NL*NR*ND];
static __device__ float g_wqkv[NL*ND*N3];  // packed [l][k][q|k|v]
static __device__ float g_bqkv[NL*N3];

// ---------------- helpers ----------------
__device__ __forceinline__ float gelu_f(float x) {
    float x3 = x * x * x;
    float t = tanhf(0.7978845608028654f * (x + 0.044715f * x3));
    return 0.5f * x * (1.0f + t);
}

__device__ __forceinline__ float blk_sum(float v, volatile float* red, int tid) {
    #pragma unroll
    for (int o = 16; o; o >>= 1) v += __shfl_xor_sync(0xffffffffu, v, o);
    if ((tid & 31) == 0) red[tid >> 5] = v;
    __syncthreads();
    float tot = 0.f;
    #pragma unroll
    for (int i = 0; i < 8; i++) tot += red[i];
    return tot;
}

// ---------------- x_in = u + seg_emb[segment_ids]; also writes z[0] ----------------
__global__ __launch_bounds__(256) void xin_kernel(
    const float* __restrict__ u, const int* __restrict__ seg,
    const float* __restrict__ semb, float* __restrict__ z0)
{
    int idx = blockIdx.x * 256 + threadIdx.x;
    int srow = idx / ND;
    int d = idx - srow * ND;
    float val = u[idx] + semb[seg[srow] * ND + d];
    g_xin[idx] = val;
    z0[idx] = val;
}

// ---------------- pack Wq|Wk|Wv -> [L][768][2304], biases too ----------------
__global__ __launch_bounds__(256) void pack_qkv_kernel(
    const float* __restrict__ Wq, const float* __restrict__ Wk, const float* __restrict__ Wv,
    const float* __restrict__ bq, const float* __restrict__ bk, const float* __restrict__ bv)
{
    int idx = blockIdx.x * 256 + threadIdx.x;   // 0 .. NL*ND*N3-1
    int l = idx / (ND * N3);
    int r = idx - l * (ND * N3);
    int kk = r / N3;
    int n = r - kk * N3;
    int which = n / ND;
    int nn = n - which * ND;
    const float* W = (which == 0) ? Wq : (which == 1) ? Wk : Wv;
    g_wqkv[idx] = W[((size_t)l * ND + kk) * ND + nn];
    if (idx < NL * N3) {
        int ll = idx / N3;
        int n2 = idx - ll * N3;
        int wh = n2 / ND, nn2 = n2 - wh * ND;
        const float* bb = (wh == 0) ? bq : (wh == 1) ? bk : bv;
        g_bqkv[idx] = bb[ll * ND + nn2];
    }
}

// ---------------- layer-0 closed-form spike rate ----------------
// cnt_t = clamp(floor(t*c), 0, t); prev = cnt/t  (t = step index + 1)
__global__ __launch_bounds__(256) void rate0_kernel(
    float tplus1, float* __restrict__ zout)
{
    int idx = blockIdx.x * 256 + threadIdx.x;
    float c = g_cur0[idx];
    float f = floorf(tplus1 * c);
    f = fminf(fmaxf(f, 0.0f), tplus1);
    float r = f / tplus1;
    g_prev[idx] = r;
    if (zout) zout[idx] = r;
}

// ---------------- fp32 tiled GEMM: 64x64 tile, double-buffered, split-K via blockIdx.z ----
// C[M=1024,N] (+bias if bias!=null) = A[M,K-slice] @ W[K-slice,N]; partial slabs when gridDim.z>1
__global__ __launch_bounds__(256) void gemm64(
    const float* __restrict__ A, const float* __restrict__ W,
    const float* __restrict__ bias, float* __restrict__ C,
    int N, int K, int klen, int do_gelu)
{
    __shared__ float As[2][16][68];
    __shared__ float Ws[2][16][64];

    const int bx = blockIdx.x, by = blockIdx.y, bz = blockIdx.z;
    const int tid = threadIdx.x;
    const int tx = tid & 15, ty = tid >> 4;
    const int arow = tid >> 2, acol = (tid & 3) << 2;
    const int wrow = tid >> 4, wcol = (tid & 15) << 2;
    const int k0 = bz * klen;

    const float* Ap = A + (size_t)(by * 64 + arow) * K + k0 + acol;
    const float* Wp = W + (size_t)(k0 + wrow) * N + bx * 64 + wcol;
    if (gridDim.z > 1) C += (size_t)bz * ((size_t)NR * N);

    float acc[4][4] = {};
    const int nkt = klen >> 4;

    float4 av = *(const float4*)Ap;
    float4 wv = *(const float4*)Wp;
    As[0][acol + 0][arow] = av.x;
    As[0][acol + 1][arow] = av.y;
    As[0][acol + 2][arow] = av.z;
    As[0][acol + 3][arow] = av.w;
    *(float4*)&Ws[0][wrow][wcol] = wv;
    __syncthreads();

    for (int kt = 0; kt < nkt; kt++) {
        const int cur = kt & 1;
        if (kt + 1 < nkt) {
            av = *(const float4*)(Ap + (kt + 1) * 16);
            wv = *(const float4*)(Wp + (size_t)(kt + 1) * 16 * N);
        }
        #pragma unroll
        for (int kk = 0; kk < 16; kk++) {
            float4 a = *(const float4*)&As[cur][kk][ty * 4];
            float4 b = *(const float4*)&Ws[cur][kk][tx * 4];
            acc[0][0] = fmaf(a.x, b.x, acc[0][0]); acc[0][1] = fmaf(a.x, b.y, acc[0][1]);
            acc[0][2] = fmaf(a.x, b.z, acc[0][2]); acc[0][3] = fmaf(a.x, b.w, acc[0][3]);
            acc[1][0] = fmaf(a.y, b.x, acc[1][0]); acc[1][1] = fmaf(a.y, b.y, acc[1][1]);
            acc[1][2] = fmaf(a.y, b.z, acc[1][2]); acc[1][3] = fmaf(a.y, b.w, acc[1][3]);
            acc[2][0] = fmaf(a.z, b.x, acc[2][0]); acc[2][1] = fmaf(a.z, b.y, acc[2][1]);
            acc[2][2] = fmaf(a.z, b.z, acc[2][2]); acc[2][3] = fmaf(a.z, b.w, acc[2][3]);
            acc[3][0] = fmaf(a.w, b.x, acc[3][0]); acc[3][1] = fmaf(a.w, b.y, acc[3][1]);
            acc[3][2] = fmaf(a.w, b.z, acc[3][2]); acc[3][3] = fmaf(a.w, b.w, acc[3][3]);
        }
        if (kt + 1 < nkt) {
            const int nx = cur ^ 1;
            As[nx][acol + 0][arow] = av.x;
            As[nx][acol + 1][arow] = av.y;
            As[nx][acol + 2][arow] = av.z;
            As[nx][acol + 3][arow] = av.w;
            *(float4*)&Ws[nx][wrow][wcol] = wv;
        }
        __syncthreads();
    }

    const int n0 = bx * 64 + tx * 4;
    #pragma unroll
    for (int i = 0; i < 4; i++) {
        const int m = by * 64 + ty * 4 + i;
        float4 o;
        o.x = acc[i][0]; o.y = acc[i][1]; o.z = acc[i][2]; o.w = acc[i][3];
        if (bias) {
            o.x += bias[n0 + 0]; o.y += bias[n0 + 1];
            o.z += bias[n0 + 2]; o.w += bias[n0 + 3];
        }
        if (do_gelu) {
            o.x = gelu_f(o.x); o.y = gelu_f(o.y); o.z = gelu_f(o.z); o.w = gelu_f(o.w);
        }
        *(float4*)&C[(size_t)m * N + n0] = o;
    }
}

// ---------------- fused attention on packed qkv (row stride 2304) ----------------
#define ATTN_SMEM_FLOATS (64*257 + 256*64 + 64*256 + 64*64)

__global__ __launch_bounds__(256) void attn_kernel(
    const float* __restrict__ qkv, const float* __restrict__ mask,
    float* __restrict__ asum, float* __restrict__ ctx,
    float wgt, int accum)
{
    extern __shared__ float sm[];
    float* Ks = sm;                     // [64][257]
    float* Vs = sm + 64 * 257;          // [256][64]
    float* Ss = Vs + 256 * 64;          // [64][256]
    float* Qs = Ss + 64 * 256;          // [64][64]

    const int rb = blockIdx.x, h = blockIdx.y, b = blockIdx.z;
    const int tid = threadIdx.x;
    const int lane = tid & 31, w = tid >> 5;
    const int i0 = rb * 64;

    const int dq = (tid & 15) * 4;
    const int jb = tid >> 4;

    const float* qb = qkv + ((size_t)b * NS + i0) * N3 + h * NDH;
    const float* kb = qkv + (size_t)b * NS * N3 + ND + h * NDH;
    const float* vb = qkv + (size_t)b * NS * N3 + 2 * ND + h * NDH;

    #pragma unroll
    for (int it = 0; it < 16; it++) {
        int j = jb + it * 16;
        float4 kv = *(const float4*)(kb + (size_t)j * N3 + dq);
        Ks[(dq + 0) * 257 + j] = kv.x;
        Ks[(dq + 1) * 257 + j] = kv.y;
        Ks[(dq + 2) * 257 + j] = kv.z;
        Ks[(dq + 3) * 257 + j] = kv.w;
        float4 vv = *(const float4*)(vb + (size_t)j * N3 + dq);
        *(float4*)&Vs[j * 64 + dq] = vv;
    }
    #pragma unroll
    for (int it = 0; it < 4; it++) {
        int i = jb + it * 16;
        float4 qv = *(const float4*)(qb + (size_t)i * N3 + dq);
        *(float4*)&Qs[i * 64 + dq] = qv;
    }
    __syncthreads();

    float extr[8];
    #pragma unroll
    for (int jj = 0; jj < 8; jj++)
        extr[jj] = (1.0f - mask[b * NS + lane + 32 * jj]) * -10000.0f;

    float acc[8][8];
    #pragma unroll
    for (int r = 0; r < 8; r++)
        #pragma unroll
        for (int jj = 0; jj < 8; jj++) acc[r][jj] = 0.f;

    const int r0 = w * 8;
    for (int d = 0; d < 64; d++) {
        float kr[8];
        #pragma unroll
        for (int jj = 0; jj < 8; jj++) kr[jj] = Ks[d * 257 + lane + 32 * jj];
        #pragma unroll
        for (int r = 0; r < 8; r++) {
            float qv = Qs[(r0 + r) * 64 + d];
            #pragma unroll
            for (int jj = 0; jj < 8; jj++) acc[r][jj] = fmaf(qv, kr[jj], acc[r][jj]);
        }
    }

    #pragma unroll
    for (int r = 0; r < 8; r++) {
        float mx = -3.0e38f;
        #pragma unroll
        for (int jj = 0; jj < 8; jj++) {
            float s = acc[r][jj] * 0.125f + extr[jj];
            acc[r][jj] = s;
            mx = fmaxf(mx, s);
        }
        #pragma unroll
        for (int o = 16; o; o >>= 1) mx = fmaxf(mx, __shfl_xor_sync(0xffffffffu, mx, o));
        float sum = 0.f;
        #pragma unroll
        for (int jj = 0; jj < 8; jj++) { float e = expf(acc[r][jj] - mx); acc[r][jj] = e; sum += e; }
        #pragma unroll
        for (int o = 16; o; o >>= 1) sum += __shfl_xor_sync(0xffffffffu, sum, o);
        float rinv = 1.0f / sum;
        int i = r0 + r;
        float* ar = asum + (((size_t)(b * NH + h)) * NS + (i0 + i)) * NS;
        #pragma unroll
        for (int jj = 0; jj < 8; jj++) {
            float p = acc[r][jj] * rinv;
            int j = lane + 32 * jj;
            Ss[i * 256 + j] = p;
            ar[j] = accum ? (ar[j] + p * wgt) : (p * wgt);
        }
    }
    __syncwarp();

    float c0[8], c1[8];
    #pragma unroll
    for (int r = 0; r < 8; r++) { c0[r] = 0.f; c1[r] = 0.f; }
    for (int j = 0; j < 256; j++) {
        float v0 = Vs[j * 64 + lane];
        float v1 = Vs[j * 64 + lane + 32];
        #pragma unroll
        for (int r = 0; r < 8; r++) {
            float p = Ss[(r0 + r) * 256 + j];
            c0[r] = fmaf(p, v0, c0[r]);
            c1[r] = fmaf(p, v1, c1[r]);
        }
    }
    #pragma unroll
    for (int r = 0; r < 8; r++) {
        size_t base = ((size_t)b * NS + i0 + r0 + r) * ND + h * NDH;
        ctx[base + lane] = c0[r];
        ctx[base + lane + 32] = c1[r];
    }
}

// ---------------- fused: residual + 2 split-K partials + bias + LayerNorm ----------------
__global__ __launch_bounds__(256) void add_ln2_kernel(
    const float* __restrict__ x, const float* __restrict__ part,
    const float* __restrict__ gbias,
    const float* __restrict__ g, const float* __restrict__ bb,
    float* __restrict__ out)
{
    __shared__ float redA[8], redB[8];
    const int row = blockIdx.x, tid = threadIdx.x;
    const size_t base = (size_t)row * ND;
    float s[3];
    #pragma unroll
    for (int e = 0; e < 3; e++) {
        int col = tid + 256 * e;
        size_t idx = base + col;
        s[e] = x[idx] + part[idx] + part[idx + (size_t)NR * ND] + gbias[col];
    }
    float mean = blk_sum(s[0] + s[1] + s[2], redA, tid) * (1.0f / 768.0f);
    float d0 = s[0] - mean, d1 = s[1] - mean, d2 = s[2] - mean;
    float var = blk_sum(d0 * d0 + d1 * d1 + d2 * d2, redB, tid) * (1.0f / 768.0f);
    float rstd = 1.0f / sqrtf(var + 1e-12f);
    float dd[3] = {d0, d1, d2};
    #pragma unroll
    for (int e = 0; e < 3; e++) {
        int col = tid + 256 * e;
        out[base + col] = g[col] * dd[e] * rstd + bb[col];
    }
}

// ---------------- fused: residual + 4 partials + bias + LN + IF spike (or plain store) ----
__global__ __launch_bounds__(256) void add_ln_spike4_kernel(
    const float* __restrict__ x, const float* __restrict__ part,
    const float* __restrict__ gbias,
    const float* __restrict__ g, const float* __restrict__ bb,
    float* __restrict__ mem, float* __restrict__ cnt, float* __restrict__ prev,
    float invt, float* __restrict__ zout, int first, float* __restrict__ curout)
{
    __shared__ float redA[8], redB[8];
    const int row = blockIdx.x, tid = threadIdx.x;
    const size_t base = (size_t)row * ND;
    const size_t slab = (size_t)NR * ND;
    float s[3];
    #pragma unroll
    for (int e = 0; e < 3; e++) {
        int col = tid + 256 * e;
        size_t idx = base + col;
        s[e] = x[idx] + part[idx] + part[idx + slab] + part[idx + 2 * slab]
             + part[idx + 3 * slab] + gbias[col];
    }
    float mean = blk_sum(s[0] + s[1] + s[2], redA, tid) * (1.0f / 768.0f);
    float d0 = s[0] - mean, d1 = s[1] - mean, d2 = s[2] - mean;
    float var = blk_sum(d0 * d0 + d1 * d1 + d2 * d2, redB, tid) * (1.0f / 768.0f);
    float rstd = 1.0f / sqrtf(var + 1e-12f);
    float dd[3] = {d0, d1, d2};

    #pragma unroll
    for (int e = 0; e < 3; e++) {
        int col = tid + 256 * e;
        size_t idx = base + col;
        float cur = g[col] * dd[e] * rstd + bb[col];
        if (curout) {
            curout[idx] = cur;
        } else {
            float m = (first ? 0.0f : mem[idx]) + cur;
            float spk = (m >= 1.0f) ? 1.0f : 0.0f;
            mem[idx] = m - spk;
            float cn = (first ? 0.0f : cnt[idx]) + spk;
            cnt[idx] = cn;
            float pv = cn * invt;
            prev[idx] = pv;
            if (zout) zout[idx] = pv;
        }
    }
}

// ---------------- launch ----------------
extern "C" void kernel_launch(void* const* d_in, const int* in_sizes, int n_in,
                              void* d_out, int out_size)
{
    const float* u    = (const float*)d_in[0];
    const int*   seg  = (const int*)d_in[1];
    const float* mask = (const float*)d_in[2];
    const float* semb = (const float*)d_in[3];
    const float* Wq   = (const float*)d_in[4];  const float* bq = (const float*)d_in[5];
    const float* Wk   = (const float*)d_in[6];  const float* bk = (const float*)d_in[7];
    const float* Wv   = (const float*)d_in[8];  const float* bv = (const float*)d_in[9];
    const float* Wo   = (const float*)d_in[10]; const float* bo = (const float*)d_in[11];
    const float* ln1g = (const float*)d_in[12]; const float* ln1b = (const float*)d_in[13];
    const float* W1   = (const float*)d_in[14]; const float* b1 = (const float*)d_in[15];
    const float* W2   = (const float*)d_in[16]; const float* b2 = (const float*)d_in[17];
    const float* ln2g = (const float*)d_in[18]; const float* ln2b = (const float*)d_in[19];
    // d_in[20] = time_step (always 6)

    float* out  = (float*)d_out;
    float* z    = out;                              // [5,B,S,D]
    float* attn = out + (size_t)5 * NR * ND;        // [L,B,H,S,S]

    void* p;
    float *xin, *prev, *qkv, *ctx, *aout, *x1, *fout, *ffh, *cur0, *mem, *cnt, *wqkv, *bqkv;
    cudaGetSymbolAddress(&p, g_xin);  xin  = (float*)p;
    cudaGetSymbolAddress(&p, g_prev); prev = (float*)p;
    cudaGetSymbolAddress(&p, g_qkv);  qkv  = (float*)p;
    cudaGetSymbolAddress(&p, g_ctx);  ctx  = (float*)p;
    cudaGetSymbolAddress(&p, g_aout); aout = (float*)p;
    cudaGetSymbolAddress(&p, g_x1);   x1   = (float*)p;
    cudaGetSymbolAddress(&p, g_fout); fout = (float*)p;
    cudaGetSymbolAddress(&p, g_ffh);  ffh  = (float*)p;
    cudaGetSymbolAddress(&p, g_cur0); cur0 = (float*)p;
    cudaGetSymbolAddress(&p, g_mem);  mem  = (float*)p;
    cudaGetSymbolAddress(&p, g_cnt);  cnt  = (float*)p;
    cudaGetSymbolAddress(&p, g_wqkv); wqkv = (float*)p;
    cudaGetSymbolAddress(&p, g_bqkv); bqkv = (float*)p;

    cudaFuncSetAttribute(attn_kernel, cudaFuncAttributeMaxDynamicSharedMemorySize,
                         ATTN_SMEM_FLOATS * 4);

    xin_kernel<<<(NR * ND) / 256, 256>>>(u, seg, semb, z);
    pack_qkv_kernel<<<(NL * ND * N3) / 256, 256>>>(Wq, Wk, Wv, bq, bk, bv);

    const dim3 gQKV(N3 / 64, NR / 64, 1);    // 36x16
    const dim3 gO  (ND / 64, NR / 64, 2);    // 12x16x2 split-K
    const dim3 gF1 (NF / 64, NR / 64, 1);    // 48x16
    const dim3 gF2 (ND / 64, NR / 64, 4);    // 12x16x4 split-K
    const dim3 gAttn(4, NH, NB);
    const float inv6 = 1.0f / 6.0f;

    // ---- layer 0: block output is constant across time steps; compute once ----
    {
        const int l = 0;
        gemm64<<<gQKV, 256>>>(xin, wqkv, bqkv, qkv, N3, ND, ND, 0);
        attn_kernel<<<gAttn, 256, ATTN_SMEM_FLOATS * 4>>>(
            qkv, mask, attn, ctx, 1.0f, 0);
        gemm64<<<gO, 256>>>(ctx, Wo + (size_t)l * ND * ND, 0, aout, ND, ND, ND / 2, 0);
        add_ln2_kernel<<<NR, 256>>>(xin, aout, bo + l * ND, ln1g + l * ND, ln1b + l * ND, x1);
        gemm64<<<gF1, 256>>>(x1, W1 + (size_t)l * ND * NF, b1 + l * NF, ffh, NF, ND, ND, 1);
        gemm64<<<gF2, 256>>>(ffh, W2 + (size_t)l * NF * ND, 0, fout, ND, NF, NF / 4, 0);
        add_ln_spike4_kernel<<<NR, 256>>>(x1, fout, b2 + l * ND, ln2g + l * ND, ln2b + l * ND,
            0, 0, 0, 0.f, 0, 0, cur0);
    }

    for (int t = 0; t < NT; t++) {
        float tp1 = (float)(t + 1);
        float invt = 1.0f / tp1;
        // layer-0 spike rate via closed form; at t=5 also writes z[1]
        rate0_kernel<<<(NR * ND) / 256, 256>>>(tp1,
            (t == NT - 1) ? (z + (size_t)1 * NR * ND) : (float*)0);

        const float* xcur = prev;
        for (int l = 1; l < NL; l++) {
            gemm64<<<gQKV, 256>>>(xcur, wqkv + (size_t)l * ND * N3, bqkv + l * N3,
                                  qkv, N3, ND, ND, 0);
            attn_kernel<<<gAttn, 256, ATTN_SMEM_FLOATS * 4>>>(
                qkv, mask, attn + (size_t)l * NB * NH * NS * NS, ctx, inv6, (t > 0) ? 1 : 0);
            gemm64<<<gO, 256>>>(ctx, Wo + (size_t)l * ND * ND, 0, aout, ND, ND, ND / 2, 0);
            add_ln2_kernel<<<NR, 256>>>(xcur, aout, bo + l * ND,
                                        ln1g + l * ND, ln1b + l * ND, x1);
            gemm64<<<gF1, 256>>>(x1, W1 + (size_t)l * ND * NF, b1 + l * NF, ffh, NF, ND, ND, 1);
            gemm64<<<gF2, 256>>>(ffh, W2 + (size_t)l * NF * ND, 0, fout, ND, NF, NF / 4, 0);
            add_ln_spike4_kernel<<<NR, 256>>>(x1, fout, b2 + l * ND,
                ln2g + l * ND, ln2b + l * ND,
                mem + (size_t)l * NR * ND, cnt + (size_t)l * NR * ND, prev, invt,
                (t == NT - 1) ? (z + (size_t)(1 + l) * NR * ND) : (float*)0,
                (t == 0) ? 1 : 0, 0);
            xcur = prev;
        }
    }
}